// round 1
// baseline (speedup 1.0000x reference)
#include <cuda_runtime.h>
#include <math.h>

#define BM 128
#define BN 128
#define BKd 8
#define TM 8
#define TN 8

static constexpr int cB    = 4096;
static constexpr int cT    = 32;
static constexpr int cA    = 3;
static constexpr int cFLAT = 96;      // T*A
static constexpr int cHID  = 1024;
static constexpr int cD    = 128;
static constexpr int cN    = 16;
static constexpr int cK    = 4096;
static constexpr int cLAT  = 2048;    // N*D
static constexpr int cROWS = cB * cN;               // 65536
static constexpr int RECON_ELEMS = cB * cT * cA;    // 393216
static constexpr int IDX_OFF     = RECON_ELEMS;     // 393216
static constexpr int SCALAR_OFF  = IDX_OFF + cROWS; // 458752
static constexpr int FULL_OUT    = SCALAR_OFF + 3;  // 458755

// ---------------- scratch (static device globals; no allocs) ----------------
__device__ float g_h1 [cB * cHID];
__device__ float g_h2 [cB * cHID];
__device__ float g_lat[cB * cLAT];
__device__ float g_q  [cB * cLAT];
__device__ float g_g1 [cB * cHID];
__device__ float g_g2 [cB * cHID];
__device__ float g_cbT[cD * cK];     // codebook transposed [D][K]
__device__ float g_cn [cK];          // ||c||^2 per code (fp64->fp32)
__device__ float g_rn [cROWS];       // ||latent row||^2 (fp64->fp32)
__device__ int   g_idx[cROWS];
__device__ float g_vq_sum;
__device__ float g_recon_sum;

// ---------------- helpers ----------------
__device__ __forceinline__ float silu_f(float x) {
    // numerically-stable logistic, matches jax expit closely
    float s;
    if (x >= 0.0f) {
        s = 1.0f / (1.0f + expf(-x));
    } else {
        float e = expf(x);
        s = e / (1.0f + e);
    }
    return x * s;
}

__global__ void init_accum() {
    g_vq_sum = 0.0f;
    g_recon_sum = 0.0f;
}

// codebook [K][D] -> cbT [D][K]
__global__ void prep_cbT(const float* __restrict__ cb) {
    int gid = blockIdx.x * 256 + threadIdx.x;
    if (gid < cD * cK) {
        int d = gid / cK;
        int k = gid - d * cK;
        g_cbT[gid] = cb[k * cD + d];
    }
}

// ||c_k||^2 in fp64, rounded to fp32. one warp per code.
__global__ void cn_kernel(const float* __restrict__ cb) {
    int warp = (blockIdx.x * blockDim.x + threadIdx.x) >> 5;
    int lane = threadIdx.x & 31;
    if (warp >= cK) return;
    const float4 v = reinterpret_cast<const float4*>(cb)[warp * 32 + lane];
    double a = (double)v.x * v.x + (double)v.y * v.y + (double)v.z * v.z + (double)v.w * v.w;
#pragma unroll
    for (int off = 16; off > 0; off >>= 1) a += __shfl_down_sync(0xffffffffu, a, off);
    if (lane == 0) g_cn[warp] = (float)a;
}

// ||latent row||^2 in fp64, rounded to fp32. one warp per row.
__global__ void rn_kernel() {
    int warp = (blockIdx.x * blockDim.x + threadIdx.x) >> 5;
    int lane = threadIdx.x & 31;
    if (warp >= cROWS) return;
    const float4 v = reinterpret_cast<const float4*>(g_lat)[(size_t)warp * 32 + lane];
    double a = (double)v.x * v.x + (double)v.y * v.y + (double)v.z * v.z + (double)v.w * v.w;
#pragma unroll
    for (int off = 16; off > 0; off >>= 1) a += __shfl_down_sync(0xffffffffu, a, off);
    if (lane == 0) g_rn[warp] = (float)a;
}

// ---------------- SGEMM: C = act(A @ B + bias) ----------------
// MODE 0: bias only   MODE 1: bias + silu   MODE 2: bias, write C, accumulate (C-ref)^2
template <int MODE>
__global__ void __launch_bounds__(256)
sgemm_k(const float* __restrict__ Ag, const float* __restrict__ Bg,
        const float* __restrict__ bias, float* __restrict__ Cg,
        int M, int N, int Kd, const float* __restrict__ ref) {
    __shared__ float As[BKd][BM];
    __shared__ float Bs[BKd][BN];

    const int tid   = threadIdx.x;
    const int rbase = blockIdx.y * BM;
    const int cbase = blockIdx.x * BN;
    const int rowA  = tid >> 1;
    const int colA4 = (tid & 1) * 4;
    const int rowB  = tid >> 5;
    const int colB4 = (tid & 31) * 4;
    const int tr    = (tid >> 4) * TM;
    const int tc    = (tid & 15) * TN;

    float acc[TM][TN];
#pragma unroll
    for (int i = 0; i < TM; i++)
#pragma unroll
        for (int j = 0; j < TN; j++) acc[i][j] = 0.0f;

    const int nt = Kd / BKd;
    for (int t = 0; t < nt; t++) {
        float4 av = *reinterpret_cast<const float4*>(
            &Ag[(size_t)(rbase + rowA) * Kd + t * BKd + colA4]);
        As[colA4 + 0][rowA] = av.x;
        As[colA4 + 1][rowA] = av.y;
        As[colA4 + 2][rowA] = av.z;
        As[colA4 + 3][rowA] = av.w;
        float4 bv = make_float4(0.f, 0.f, 0.f, 0.f);
        if (cbase + colB4 < N)
            bv = *reinterpret_cast<const float4*>(
                &Bg[(size_t)(t * BKd + rowB) * N + cbase + colB4]);
        *reinterpret_cast<float4*>(&Bs[rowB][colB4]) = bv;
        __syncthreads();
#pragma unroll
        for (int k = 0; k < BKd; k++) {
            float rM[TM], rN[TN];
#pragma unroll
            for (int i = 0; i < TM; i++) rM[i] = As[k][tr + i];
#pragma unroll
            for (int j = 0; j < TN; j++) rN[j] = Bs[k][tc + j];
#pragma unroll
            for (int i = 0; i < TM; i++)
#pragma unroll
                for (int j = 0; j < TN; j++) acc[i][j] = fmaf(rM[i], rN[j], acc[i][j]);
        }
        __syncthreads();
    }

    float lsum = 0.0f;
#pragma unroll
    for (int i = 0; i < TM; i++) {
        const int row = rbase + tr + i;
#pragma unroll
        for (int j = 0; j < TN; j++) {
            const int col = cbase + tc + j;
            if (col < N) {
                float v = acc[i][j] + bias[col];
                if (MODE == 1) v = silu_f(v);
                Cg[(size_t)row * N + col] = v;
                if (MODE == 2) {
                    float d = v - ref[(size_t)row * N + col];
                    lsum = fmaf(d, d, lsum);
                }
            }
        }
    }
    if (MODE == 2) {
        __shared__ float red[256];
        red[tid] = lsum;
        __syncthreads();
        for (int s = 128; s > 0; s >>= 1) {
            if (tid < s) red[tid] += red[tid + s];
            __syncthreads();
        }
        if (tid == 0) atomicAdd(&g_recon_sum, red[0]);
    }
}

// ---------------- argmin over codes (GEMM-structured) ----------------
// dist replicates reference rounding: fl( fl(rn+cn) - fl(2*dot) )
__global__ void __launch_bounds__(256)
argmin_kernel() {
    __shared__ float As[BKd][BM];
    __shared__ float Bs[BKd][BN];
    __shared__ float rVal[BM][16];
    __shared__ int   rIdx[BM][16];

    const int tid   = threadIdx.x;
    const int rbase = blockIdx.x * BM;
    const int rowA  = tid >> 1;
    const int colA4 = (tid & 1) * 4;
    const int rowB  = tid >> 5;
    const int colB4 = (tid & 31) * 4;
    const int tr    = (tid >> 4) * TM;
    const int tc    = (tid & 15) * TN;

    float rnv[TM];
#pragma unroll
    for (int i = 0; i < TM; i++) rnv[i] = g_rn[rbase + tr + i];

    float bestV[TM];
    int   bestI[TM];
#pragma unroll
    for (int i = 0; i < TM; i++) { bestV[i] = INFINITY; bestI[i] = 0; }

    for (int ct = 0; ct < cK / BN; ct++) {
        float acc[TM][TN];
#pragma unroll
        for (int i = 0; i < TM; i++)
#pragma unroll
            for (int j = 0; j < TN; j++) acc[i][j] = 0.0f;

        for (int kc = 0; kc < cD / BKd; kc++) {
            float4 av = *reinterpret_cast<const float4*>(
                &g_lat[(size_t)(rbase + rowA) * cD + kc * BKd + colA4]);
            As[colA4 + 0][rowA] = av.x;
            As[colA4 + 1][rowA] = av.y;
            As[colA4 + 2][rowA] = av.z;
            As[colA4 + 3][rowA] = av.w;
            float4 bv = *reinterpret_cast<const float4*>(
                &g_cbT[(size_t)(kc * BKd + rowB) * cK + ct * BN + colB4]);
            *reinterpret_cast<float4*>(&Bs[rowB][colB4]) = bv;
            __syncthreads();
#pragma unroll
            for (int k = 0; k < BKd; k++) {
                float rM[TM], rN[TN];
#pragma unroll
                for (int i = 0; i < TM; i++) rM[i] = As[k][tr + i];
#pragma unroll
                for (int j = 0; j < TN; j++) rN[j] = Bs[k][tc + j];
#pragma unroll
                for (int i = 0; i < TM; i++)
#pragma unroll
                    for (int j = 0; j < TN; j++) acc[i][j] = fmaf(rM[i], rN[j], acc[i][j]);
            }
            __syncthreads();
        }
        // score epilogue for this code tile
#pragma unroll
        for (int j = 0; j < TN; j++) {
            const int kg = ct * BN + tc + j;
            const float cnk = __ldg(&g_cn[kg]);
#pragma unroll
            for (int i = 0; i < TM; i++) {
                float s1   = __fadd_rn(rnv[i], cnk);
                float dist = __fadd_rn(s1, -2.0f * acc[i][j]);
                if (dist < bestV[i]) { bestV[i] = dist; bestI[i] = kg; }
            }
        }
    }

#pragma unroll
    for (int i = 0; i < TM; i++) {
        rVal[tr + i][tid & 15] = bestV[i];
        rIdx[tr + i][tid & 15] = bestI[i];
    }
    __syncthreads();
    if (tid < BM) {
        float bv = rVal[tid][0];
        int   bi = rIdx[tid][0];
#pragma unroll
        for (int c = 1; c < 16; c++) {
            float v = rVal[tid][c];
            int   ix = rIdx[tid][c];
            if (v < bv || (v == bv && ix < bi)) { bv = v; bi = ix; }
        }
        g_idx[rbase + tid] = bi;
    }
}

// gather quantized rows, accumulate vq sum, emit indices as float
__global__ void gather_vq(const float* __restrict__ cb, float* __restrict__ outIdxF) {
    int warp = (blockIdx.x * blockDim.x + threadIdx.x) >> 5;
    int lane = threadIdx.x & 31;
    if (warp >= cROWS) return;
    int id = g_idx[warp];
    float4 c = reinterpret_cast<const float4*>(cb)[(size_t)id * 32 + lane];
    float4 l = reinterpret_cast<const float4*>(g_lat)[(size_t)warp * 32 + lane];
    reinterpret_cast<float4*>(g_q)[(size_t)warp * 32 + lane] = c;
    float dx = c.x - l.x, dy = c.y - l.y, dz = c.z - l.z, dw = c.w - l.w;
    float s = dx * dx + dy * dy + dz * dz + dw * dw;
#pragma unroll
    for (int off = 16; off > 0; off >>= 1) s += __shfl_down_sync(0xffffffffu, s, off);
    if (lane == 0) {
        atomicAdd(&g_vq_sum, s);
        if (outIdxF) outIdxF[warp] = (float)id;
    }
}

__global__ void finalize_k(float* __restrict__ out, int out_size) {
    if (out_size >= FULL_OUT) {
        float m  = g_vq_sum / (float)(cB * cN * cD);
        float vq = 1.25f * m;
        float rl = g_recon_sum / (float)RECON_ELEMS;
        out[SCALAR_OFF + 0] = vq;
        out[SCALAR_OFF + 1] = rl;
        out[SCALAR_OFF + 2] = rl + vq;
    }
}

// ---------------- launch ----------------
extern "C" void kernel_launch(void* const* d_in, const int* in_sizes, int n_in,
                              void* d_out, int out_size) {
    const float* actions = (const float*)d_in[0];
    const float* e_w1 = (const float*)d_in[1];
    const float* e_b1 = (const float*)d_in[2];
    const float* e_w2 = (const float*)d_in[3];
    const float* e_b2 = (const float*)d_in[4];
    const float* e_w3 = (const float*)d_in[5];
    const float* e_b3 = (const float*)d_in[6];
    const float* cb   = (const float*)d_in[7];
    const float* d_w1 = (const float*)d_in[8];
    const float* d_b1 = (const float*)d_in[9];
    const float* d_w2 = (const float*)d_in[10];
    const float* d_b2 = (const float*)d_in[11];
    const float* d_w3 = (const float*)d_in[12];
    const float* d_b3 = (const float*)d_in[13];
    float* out = (float*)d_out;

    float *p_h1, *p_h2, *p_lat, *p_q, *p_g1, *p_g2;
    cudaGetSymbolAddress((void**)&p_h1,  g_h1);
    cudaGetSymbolAddress((void**)&p_h2,  g_h2);
    cudaGetSymbolAddress((void**)&p_lat, g_lat);
    cudaGetSymbolAddress((void**)&p_q,   g_q);
    cudaGetSymbolAddress((void**)&p_g1,  g_g1);
    cudaGetSymbolAddress((void**)&p_g2,  g_g2);

    const bool has_idx = out_size >= (IDX_OFF + cROWS);

    init_accum<<<1, 1>>>();
    prep_cbT<<<(cD * cK + 255) / 256, 256>>>(cb);
    cn_kernel<<<cK / 8, 256>>>(cb);

    // encoder
    sgemm_k<1><<<dim3(cHID / BN, cB / BM), 256>>>(actions, e_w1, e_b1, p_h1, cB, cHID, cFLAT, nullptr);
    sgemm_k<1><<<dim3(cHID / BN, cB / BM), 256>>>(p_h1, e_w2, e_b2, p_h2, cB, cHID, cHID, nullptr);
    sgemm_k<0><<<dim3(cLAT / BN, cB / BM), 256>>>(p_h2, e_w3, e_b3, p_lat, cB, cLAT, cHID, nullptr);

    // quantization
    rn_kernel<<<cROWS / 8, 256>>>();
    argmin_kernel<<<cROWS / BM, 256>>>();
    gather_vq<<<cROWS / 8, 256>>>(cb, has_idx ? (out + IDX_OFF) : nullptr);

    // decoder (dec3 writes recon into d_out and accumulates recon loss)
    sgemm_k<1><<<dim3(cHID / BN, cB / BM), 256>>>(p_q, d_w1, d_b1, p_g1, cB, cHID, cLAT, nullptr);
    sgemm_k<1><<<dim3(cHID / BN, cB / BM), 256>>>(p_g1, d_w2, d_b2, p_g2, cB, cHID, cHID, nullptr);
    sgemm_k<2><<<dim3(1, cB / BM), 256>>>(p_g2, d_w3, d_b3, out, cB, cFLAT, cHID, actions);

    finalize_k<<<1, 1>>>(out, out_size);
}

// round 2
// speedup vs baseline: 1.0077x; 1.0077x over previous
#include <cuda_runtime.h>
#include <math.h>

#define BM 128
#define BN 128
#define BKd 8
#define TM 8
#define TN 8

static constexpr int cB    = 4096;
static constexpr int cT    = 32;
static constexpr int cA    = 3;
static constexpr int cFLAT = 96;      // T*A
static constexpr int cHID  = 1024;
static constexpr int cD    = 128;
static constexpr int cN    = 16;
static constexpr int cK    = 4096;
static constexpr int cLAT  = 2048;    // N*D
static constexpr int cROWS = cB * cN;               // 65536
static constexpr int RECON_ELEMS = cB * cT * cA;    // 393216
static constexpr int IDX_OFF     = RECON_ELEMS;     // 393216
static constexpr int SCALAR_OFF  = IDX_OFF + cROWS; // 458752
static constexpr int FULL_OUT    = SCALAR_OFF + 3;  // 458755

static constexpr int ARG_SMEM = BM * cD * 4 + BKd * BN * 4;  // 64KB + 4KB

// ---------------- scratch (static device globals; no allocs) ----------------
__device__ float g_h1 [cB * cHID];
__device__ float g_h2 [cB * cHID];
__device__ float g_lat[cB * cLAT];
__device__ float g_q  [cB * cLAT];
__device__ float g_g1 [cB * cHID];
__device__ float g_g2 [cB * cHID];
__device__ float g_cbT[cD * cK];     // codebook transposed [D][K]
__device__ float g_cn [cK];          // ||c||^2 per code (fp64->fp32)
__device__ float g_rn [cROWS];       // ||latent row||^2 (fp64->fp32)
__device__ int   g_idx[cROWS];
__device__ float g_vq_sum;
__device__ float g_recon_sum;

// ---------------- f32x2 packed math helpers (bit-identical to 2x fp32 FMA) --
typedef unsigned long long u64;

__device__ __forceinline__ u64 pack2(float lo, float hi) {
    u64 r;
    asm("mov.b64 %0, {%1, %2};" : "=l"(r)
        : "r"(__float_as_uint(lo)), "r"(__float_as_uint(hi)));
    return r;
}
__device__ __forceinline__ void fma2(u64 &d, u64 a, u64 b) {
    asm("fma.rn.f32x2 %0, %1, %2, %0;" : "+l"(d) : "l"(a), "l"(b));
}
__device__ __forceinline__ void unpack2(u64 v, float &lo, float &hi) {
    unsigned int l, h;
    asm("mov.b64 {%0, %1}, %2;" : "=r"(l), "=r"(h) : "l"(v));
    lo = __uint_as_float(l);
    hi = __uint_as_float(h);
}

// ---------------- helpers ----------------
__device__ __forceinline__ float silu_f(float x) {
    float s;
    if (x >= 0.0f) {
        s = 1.0f / (1.0f + expf(-x));
    } else {
        float e = expf(x);
        s = e / (1.0f + e);
    }
    return x * s;
}

__global__ void init_accum() {
    g_vq_sum = 0.0f;
    g_recon_sum = 0.0f;
}

// codebook [K][D] -> cbT [D][K]
__global__ void prep_cbT(const float* __restrict__ cb) {
    int gid = blockIdx.x * 256 + threadIdx.x;
    if (gid < cD * cK) {
        int d = gid / cK;
        int k = gid - d * cK;
        g_cbT[gid] = cb[k * cD + d];
    }
}

// ||c_k||^2 in fp64, rounded to fp32. one warp per code.
__global__ void cn_kernel(const float* __restrict__ cb) {
    int warp = (blockIdx.x * blockDim.x + threadIdx.x) >> 5;
    int lane = threadIdx.x & 31;
    if (warp >= cK) return;
    const float4 v = reinterpret_cast<const float4*>(cb)[warp * 32 + lane];
    double a = (double)v.x * v.x + (double)v.y * v.y + (double)v.z * v.z + (double)v.w * v.w;
#pragma unroll
    for (int off = 16; off > 0; off >>= 1) a += __shfl_down_sync(0xffffffffu, a, off);
    if (lane == 0) g_cn[warp] = (float)a;
}

// ||latent row||^2 in fp64, rounded to fp32. one warp per row.
__global__ void rn_kernel() {
    int warp = (blockIdx.x * blockDim.x + threadIdx.x) >> 5;
    int lane = threadIdx.x & 31;
    if (warp >= cROWS) return;
    const float4 v = reinterpret_cast<const float4*>(g_lat)[(size_t)warp * 32 + lane];
    double a = (double)v.x * v.x + (double)v.y * v.y + (double)v.z * v.z + (double)v.w * v.w;
#pragma unroll
    for (int off = 16; off > 0; off >>= 1) a += __shfl_down_sync(0xffffffffu, a, off);
    if (lane == 0) g_rn[warp] = (float)a;
}

// ---------------- SGEMM (f32x2): C = act(A @ B + bias) ----------------
// MODE 0: bias only   MODE 1: bias + silu   MODE 2: bias, write C, accumulate (C-ref)^2
template <int MODE>
__global__ void __launch_bounds__(256)
sgemm_k(const float* __restrict__ Ag, const float* __restrict__ Bg,
        const float* __restrict__ bias, float* __restrict__ Cg,
        int M, int N, int Kd, const float* __restrict__ ref) {
    __shared__ float As[BKd][BM];
    __shared__ float Bs[BKd][BN];

    const int tid   = threadIdx.x;
    const int rbase = blockIdx.y * BM;
    const int cbase = blockIdx.x * BN;
    const int rowA  = tid >> 1;
    const int colA4 = (tid & 1) * 4;
    const int rowB  = tid >> 5;
    const int colB4 = (tid & 31) * 4;
    const int tr    = (tid >> 4) * TM;
    const int tc    = (tid & 15) * TN;

    u64 acc[TM][TN / 2];
#pragma unroll
    for (int i = 0; i < TM; i++)
#pragma unroll
        for (int j = 0; j < TN / 2; j++) acc[i][j] = 0ull;

    const int nt = Kd / BKd;
    // prefetch tile 0
    float4 pa = *reinterpret_cast<const float4*>(&Ag[(size_t)(rbase + rowA) * Kd + colA4]);
    float4 pb = make_float4(0.f, 0.f, 0.f, 0.f);
    if (cbase + colB4 < N)
        pb = *reinterpret_cast<const float4*>(&Bg[(size_t)rowB * N + cbase + colB4]);

    for (int t = 0; t < nt; t++) {
        __syncthreads();
        As[colA4 + 0][rowA] = pa.x;
        As[colA4 + 1][rowA] = pa.y;
        As[colA4 + 2][rowA] = pa.z;
        As[colA4 + 3][rowA] = pa.w;
        *reinterpret_cast<float4*>(&Bs[rowB][colB4]) = pb;
        __syncthreads();
        if (t + 1 < nt) {
            pa = *reinterpret_cast<const float4*>(
                &Ag[(size_t)(rbase + rowA) * Kd + (t + 1) * BKd + colA4]);
            if (cbase + colB4 < N)
                pb = *reinterpret_cast<const float4*>(
                    &Bg[(size_t)((t + 1) * BKd + rowB) * N + cbase + colB4]);
        }
#pragma unroll
        for (int k = 0; k < BKd; k++) {
            float4 a0 = *reinterpret_cast<const float4*>(&As[k][tr]);
            float4 a1 = *reinterpret_cast<const float4*>(&As[k][tr + 4]);
            const u64* bp = reinterpret_cast<const u64*>(&Bs[k][tc]);
            u64 b0 = bp[0], b1 = bp[1], b2 = bp[2], b3 = bp[3];
            float am[TM] = {a0.x, a0.y, a0.z, a0.w, a1.x, a1.y, a1.z, a1.w};
#pragma unroll
            for (int i = 0; i < TM; i++) {
                u64 ap = pack2(am[i], am[i]);
                fma2(acc[i][0], ap, b0);
                fma2(acc[i][1], ap, b1);
                fma2(acc[i][2], ap, b2);
                fma2(acc[i][3], ap, b3);
            }
        }
    }

    float lsum = 0.0f;
#pragma unroll
    for (int i = 0; i < TM; i++) {
        const int row = rbase + tr + i;
#pragma unroll
        for (int j = 0; j < TN / 2; j++) {
            const int c0 = cbase + tc + 2 * j;
            if (c0 < N) {  // N even, c0 even -> c0+1 < N too
                float lo, hi;
                unpack2(acc[i][j], lo, hi);
                float v0 = lo + bias[c0];
                float v1 = hi + bias[c0 + 1];
                if (MODE == 1) { v0 = silu_f(v0); v1 = silu_f(v1); }
                Cg[(size_t)row * N + c0]     = v0;
                Cg[(size_t)row * N + c0 + 1] = v1;
                if (MODE == 2) {
                    float d0 = v0 - ref[(size_t)row * N + c0];
                    float d1 = v1 - ref[(size_t)row * N + c0 + 1];
                    lsum = fmaf(d0, d0, fmaf(d1, d1, lsum));
                }
            }
        }
    }
    if (MODE == 2) {
        __shared__ float red[256];
        red[tid] = lsum;
        __syncthreads();
        for (int s = 128; s > 0; s >>= 1) {
            if (tid < s) red[tid] += red[tid + s];
            __syncthreads();
        }
        if (tid == 0) atomicAdd(&g_recon_sum, red[0]);
    }
}

// ---------------- argmin over codes (A resident in smem, f32x2) ----------------
// dist replicates reference rounding: fl( fl(rn+cn) - fl(2*dot) )
__global__ void __launch_bounds__(256)
argmin_kernel() {
    extern __shared__ float sm[];
    float (*As)[cD] = reinterpret_cast<float(*)[cD]>(sm);          // [BM][128] 64KB
    float (*Bs)[BN] = reinterpret_cast<float(*)[BN]>(sm + BM * cD); // [8][128]  4KB

    const int tid   = threadIdx.x;
    const int rbase = blockIdx.x * BM;
    const int rowB  = tid >> 5;
    const int colB4 = (tid & 31) * 4;
    const int tr    = (tid >> 4) * TM;
    const int tc    = (tid & 15) * TN;

    // load A block once (coalesced float4 copy, row-major)
    {
        const float4* src = reinterpret_cast<const float4*>(&g_lat[(size_t)rbase * cD]);
        float4* dst = reinterpret_cast<float4*>(sm);
        for (int i = tid; i < BM * cD / 4; i += 256) dst[i] = src[i];
    }

    float rnv[TM];
#pragma unroll
    for (int i = 0; i < TM; i++) rnv[i] = g_rn[rbase + tr + i];

    float bestV[TM];
    int   bestI[TM];
#pragma unroll
    for (int i = 0; i < TM; i++) { bestV[i] = INFINITY; bestI[i] = 0; }

    __syncthreads();

    const int NKC = cD / BKd;          // 16
    const int NCT = cK / BN;           // 32
    float4 pb = *reinterpret_cast<const float4*>(&g_cbT[(size_t)rowB * cK + colB4]);

    for (int ct = 0; ct < NCT; ct++) {
        u64 acc[TM][4];
#pragma unroll
        for (int i = 0; i < TM; i++)
#pragma unroll
            for (int j = 0; j < 4; j++) acc[i][j] = 0ull;

        for (int kc = 0; kc < NKC; kc++) {
            __syncthreads();
            *reinterpret_cast<float4*>(&Bs[rowB][colB4]) = pb;
            __syncthreads();
            int s = ct * NKC + kc + 1;
            if (s < NCT * NKC) {
                int ct2 = s / NKC, kc2 = s % NKC;
                pb = *reinterpret_cast<const float4*>(
                    &g_cbT[(size_t)(kc2 * BKd + rowB) * cK + ct2 * BN + colB4]);
            }
#pragma unroll
            for (int k = 0; k < BKd; k++) {
                const int kg = kc * BKd + k;
                const u64* bp = reinterpret_cast<const u64*>(&Bs[k][tc]);
                u64 b0 = bp[0], b1 = bp[1], b2 = bp[2], b3 = bp[3];
#pragma unroll
                for (int i = 0; i < TM; i++) {
                    float a = As[tr + i][kg];   // broadcast within 16-lane group
                    u64 ap = pack2(a, a);
                    fma2(acc[i][0], ap, b0);
                    fma2(acc[i][1], ap, b1);
                    fma2(acc[i][2], ap, b2);
                    fma2(acc[i][3], ap, b3);
                }
            }
        }
        // score epilogue for this code tile (kg ascending => first-index tie-break)
#pragma unroll
        for (int j = 0; j < 4; j++) {
            const int kg0 = ct * BN + tc + 2 * j;
            const float cn0 = __ldg(&g_cn[kg0]);
            const float cn1 = __ldg(&g_cn[kg0 + 1]);
#pragma unroll
            for (int i = 0; i < TM; i++) {
                float lo, hi;
                unpack2(acc[i][j], lo, hi);
                float s0 = __fadd_rn(rnv[i], cn0);
                float d0 = __fadd_rn(s0, -2.0f * lo);
                if (d0 < bestV[i]) { bestV[i] = d0; bestI[i] = kg0; }
                float s1 = __fadd_rn(rnv[i], cn1);
                float d1 = __fadd_rn(s1, -2.0f * hi);
                if (d1 < bestV[i]) { bestV[i] = d1; bestI[i] = kg0 + 1; }
            }
        }
    }

    // cross-thread reduction (overlay on As smem region)
    __syncthreads();
    float (*rVal)[16] = reinterpret_cast<float(*)[16]>(sm);
    int   (*rIdx)[16] = reinterpret_cast<int(*)[16]>(sm + BM * 16);
#pragma unroll
    for (int i = 0; i < TM; i++) {
        rVal[tr + i][tid & 15] = bestV[i];
        rIdx[tr + i][tid & 15] = bestI[i];
    }
    __syncthreads();
    if (tid < BM) {
        float bv = rVal[tid][0];
        int   bi = rIdx[tid][0];
#pragma unroll
        for (int c = 1; c < 16; c++) {
            float v  = rVal[tid][c];
            int   ix = rIdx[tid][c];
            if (v < bv || (v == bv && ix < bi)) { bv = v; bi = ix; }
        }
        g_idx[rbase + tid] = bi;
    }
}

// gather quantized rows, accumulate vq sum, emit indices as float
__global__ void gather_vq(const float* __restrict__ cb, float* __restrict__ outIdxF) {
    int warp = (blockIdx.x * blockDim.x + threadIdx.x) >> 5;
    int lane = threadIdx.x & 31;
    if (warp >= cROWS) return;
    int id = g_idx[warp];
    float4 c = reinterpret_cast<const float4*>(cb)[(size_t)id * 32 + lane];
    float4 l = reinterpret_cast<const float4*>(g_lat)[(size_t)warp * 32 + lane];
    reinterpret_cast<float4*>(g_q)[(size_t)warp * 32 + lane] = c;
    float dx = c.x - l.x, dy = c.y - l.y, dz = c.z - l.z, dw = c.w - l.w;
    float s = dx * dx + dy * dy + dz * dz + dw * dw;
#pragma unroll
    for (int off = 16; off > 0; off >>= 1) s += __shfl_down_sync(0xffffffffu, s, off);
    if (lane == 0) {
        atomicAdd(&g_vq_sum, s);
        if (outIdxF) outIdxF[warp] = (float)id;
    }
}

__global__ void finalize_k(float* __restrict__ out, int out_size) {
    if (out_size >= FULL_OUT) {
        float m  = g_vq_sum / (float)(cB * cN * cD);
        float vq = 1.25f * m;
        float rl = g_recon_sum / (float)RECON_ELEMS;
        out[SCALAR_OFF + 0] = vq;
        out[SCALAR_OFF + 1] = rl;
        out[SCALAR_OFF + 2] = rl + vq;
    }
}

// ---------------- launch ----------------
extern "C" void kernel_launch(void* const* d_in, const int* in_sizes, int n_in,
                              void* d_out, int out_size) {
    const float* actions = (const float*)d_in[0];
    const float* e_w1 = (const float*)d_in[1];
    const float* e_b1 = (const float*)d_in[2];
    const float* e_w2 = (const float*)d_in[3];
    const float* e_b2 = (const float*)d_in[4];
    const float* e_w3 = (const float*)d_in[5];
    const float* e_b3 = (const float*)d_in[6];
    const float* cb   = (const float*)d_in[7];
    const float* d_w1 = (const float*)d_in[8];
    const float* d_b1 = (const float*)d_in[9];
    const float* d_w2 = (const float*)d_in[10];
    const float* d_b2 = (const float*)d_in[11];
    const float* d_w3 = (const float*)d_in[12];
    const float* d_b3 = (const float*)d_in[13];
    float* out = (float*)d_out;

    float *p_h1, *p_h2, *p_lat, *p_q, *p_g1, *p_g2;
    cudaGetSymbolAddress((void**)&p_h1,  g_h1);
    cudaGetSymbolAddress((void**)&p_h2,  g_h2);
    cudaGetSymbolAddress((void**)&p_lat, g_lat);
    cudaGetSymbolAddress((void**)&p_q,   g_q);
    cudaGetSymbolAddress((void**)&p_g1,  g_g1);
    cudaGetSymbolAddress((void**)&p_g2,  g_g2);

    static bool attr_done = false;
    if (!attr_done) {
        cudaFuncSetAttribute(argmin_kernel,
                             cudaFuncAttributeMaxDynamicSharedMemorySize, ARG_SMEM);
        attr_done = true;
    }

    const bool has_idx = out_size >= (IDX_OFF + cROWS);

    init_accum<<<1, 1>>>();
    prep_cbT<<<(cD * cK + 255) / 256, 256>>>(cb);
    cn_kernel<<<cK / 8, 256>>>(cb);

    // encoder
    sgemm_k<1><<<dim3(cHID / BN, cB / BM), 256>>>(actions, e_w1, e_b1, p_h1, cB, cHID, cFLAT, nullptr);
    sgemm_k<1><<<dim3(cHID / BN, cB / BM), 256>>>(p_h1, e_w2, e_b2, p_h2, cB, cHID, cHID, nullptr);
    sgemm_k<0><<<dim3(cLAT / BN, cB / BM), 256>>>(p_h2, e_w3, e_b3, p_lat, cB, cLAT, cHID, nullptr);

    // quantization
    rn_kernel<<<cROWS / 8, 256>>>();
    argmin_kernel<<<cROWS / BM, 256, ARG_SMEM>>>();
    gather_vq<<<cROWS / 8, 256>>>(cb, has_idx ? (out + IDX_OFF) : nullptr);

    // decoder (dec3 writes recon into d_out and accumulates recon loss)
    sgemm_k<1><<<dim3(cHID / BN, cB / BM), 256>>>(p_q, d_w1, d_b1, p_g1, cB, cHID, cLAT, nullptr);
    sgemm_k<1><<<dim3(cHID / BN, cB / BM), 256>>>(p_g1, d_w2, d_b2, p_g2, cB, cHID, cHID, nullptr);
    sgemm_k<2><<<dim3(1, cB / BM), 256>>>(p_g2, d_w3, d_b3, out, cB, cFLAT, cHID, actions);

    finalize_k<<<1, 1>>>(out, out_size);
}

// round 5
// speedup vs baseline: 1.1536x; 1.1448x over previous
#include <cuda_runtime.h>
#include <cuda_fp16.h>
#include <math.h>
#include <stdint.h>

#define BM 128
#define BN 128
#define BKd 8
#define TM 8
#define TN 8

static constexpr int cB    = 4096;
static constexpr int cT    = 32;
static constexpr int cA    = 3;
static constexpr int cFLAT = 96;
static constexpr int cHID  = 1024;
static constexpr int cD    = 128;
static constexpr int cN    = 16;
static constexpr int cK    = 4096;
static constexpr int cLAT  = 2048;
static constexpr int cROWS = cB * cN;               // 65536
static constexpr int RECON_ELEMS = cB * cT * cA;    // 393216
static constexpr int IDX_OFF     = RECON_ELEMS;
static constexpr int SCALAR_OFF  = IDX_OFF + cROWS;
static constexpr int FULL_OUT    = SCALAR_OFF + 3;

// fp16 split scaling: hi = rn(x*2^8), lo = rn((x*2^8 - hi)*2^11)
static constexpr float SSCALE   = 256.0f;
static constexpr float LOSCALE  = 2048.0f;
static constexpr float INV_LO   = 4.8828125e-4f;     // 2^-11
static constexpr float INV_FULL = 1.52587890625e-5f; // 2^-16
static constexpr float EPS_SCALED = 2e-7f * 65536.0f;

// ---------------- scratch ----------------
__device__ float g_h1 [cB * cHID];
__device__ float g_h2 [cB * cHID];
__device__ float g_lat[cB * cLAT];
__device__ float g_cn [cK];
__device__ float g_rn [cROWS];
__device__ int   g_idx[cROWS];
__device__ float g_vq_sum;
__device__ float g_recon_sum;
__device__ int   g_flagcnt;
__device__ int   g_flagrows[cROWS];

__device__ __half g_latH[cROWS * cD], g_latL[cROWS * cD];
__device__ __half g_qH [cB * cLAT],   g_qL [cB * cLAT];
__device__ __half g_g1H[cB * cHID],   g_g1L[cB * cHID];
__device__ __half g_g2H[cB * cHID],   g_g2L[cB * cHID];
__device__ __half g_cbH[cK * cD],     g_cbL[cK * cD];
__device__ __half g_v1H[cHID * cLAT],  g_v1L[cHID * cLAT];
__device__ __half g_v2H[cHID * cHID],  g_v2L[cHID * cHID];
__device__ __half g_v3H[cFLAT * cHID], g_v3L[cFLAT * cHID];

// ---------------- f32x2 helpers ----------------
typedef unsigned long long u64;
__device__ __forceinline__ u64 pack2(float lo, float hi) {
    u64 r;
    asm("mov.b64 %0, {%1, %2};" : "=l"(r) : "r"(__float_as_uint(lo)), "r"(__float_as_uint(hi)));
    return r;
}
__device__ __forceinline__ void fma2(u64 &d, u64 a, u64 b) {
    asm("fma.rn.f32x2 %0, %1, %2, %0;" : "+l"(d) : "l"(a), "l"(b));
}
__device__ __forceinline__ void unpack2(u64 v, float &lo, float &hi) {
    unsigned int l, h;
    asm("mov.b64 {%0, %1}, %2;" : "=r"(l), "=r"(h) : "l"(v));
    lo = __uint_as_float(l); hi = __uint_as_float(h);
}

__device__ __forceinline__ float silu_f(float x) {
    float s;
    if (x >= 0.0f) s = 1.0f / (1.0f + expf(-x));
    else { float e = expf(x); s = e / (1.0f + e); }
    return x * s;
}

__device__ __forceinline__ void mma16816(float c[4], uint32_t a0, uint32_t a1,
                                         uint32_t a2, uint32_t a3,
                                         uint32_t b0, uint32_t b1) {
    asm volatile(
        "mma.sync.aligned.m16n8k16.row.col.f32.f16.f16.f32 "
        "{%0,%1,%2,%3},{%4,%5,%6,%7},{%8,%9},{%0,%1,%2,%3};"
        : "+f"(c[0]), "+f"(c[1]), "+f"(c[2]), "+f"(c[3])
        : "r"(a0), "r"(a1), "r"(a2), "r"(a3), "r"(b0), "r"(b1));
}

__global__ void init_accum() { g_vq_sum = 0.0f; g_recon_sum = 0.0f; g_flagcnt = 0; }

__global__ void cn_kernel(const float* __restrict__ cb) {
    int warp = (blockIdx.x * blockDim.x + threadIdx.x) >> 5;
    int lane = threadIdx.x & 31;
    if (warp >= cK) return;
    const float4 v = reinterpret_cast<const float4*>(cb)[warp * 32 + lane];
    double a = (double)v.x * v.x + (double)v.y * v.y + (double)v.z * v.z + (double)v.w * v.w;
#pragma unroll
    for (int off = 16; off > 0; off >>= 1) a += __shfl_down_sync(0xffffffffu, a, off);
    if (lane == 0) g_cn[warp] = (float)a;
}

__global__ void rn_kernel() {
    int warp = (blockIdx.x * blockDim.x + threadIdx.x) >> 5;
    int lane = threadIdx.x & 31;
    if (warp >= cROWS) return;
    const float4 v = reinterpret_cast<const float4*>(g_lat)[(size_t)warp * 32 + lane];
    double a = (double)v.x * v.x + (double)v.y * v.y + (double)v.z * v.z + (double)v.w * v.w;
#pragma unroll
    for (int off = 16; off > 0; off >>= 1) a += __shfl_down_sync(0xffffffffu, a, off);
    if (lane == 0) g_rn[warp] = (float)a;
}

__global__ void split_act(const float* __restrict__ src, __half* __restrict__ hi,
                          __half* __restrict__ lo, int n4) {
    int i = blockIdx.x * blockDim.x + threadIdx.x;
    if (i >= n4) return;
    float4 v = reinterpret_cast<const float4*>(src)[i];
    float x0 = v.x * SSCALE, x1 = v.y * SSCALE, x2 = v.z * SSCALE, x3 = v.w * SSCALE;
    __half h0 = __float2half_rn(x0), h1 = __float2half_rn(x1);
    __half h2 = __float2half_rn(x2), h3 = __float2half_rn(x3);
    __half2* hp = reinterpret_cast<__half2*>(hi);
    __half2* lp = reinterpret_cast<__half2*>(lo);
    hp[i * 2 + 0] = __half2(h0, h1);
    hp[i * 2 + 1] = __half2(h2, h3);
    lp[i * 2 + 0] = __half2(__float2half_rn((x0 - __half2float(h0)) * LOSCALE),
                            __float2half_rn((x1 - __half2float(h1)) * LOSCALE));
    lp[i * 2 + 1] = __half2(__float2half_rn((x2 - __half2float(h2)) * LOSCALE),
                            __float2half_rn((x3 - __half2float(h3)) * LOSCALE));
}

// weight transpose + split: W [Kd][N] fp32 -> [N][Kd] fp16 hi/lo
__global__ void wsplit(const float* __restrict__ W, __half* __restrict__ WtH,
                       __half* __restrict__ WtL, int Kd, int N) {
    __shared__ float tile[32][33];
    const int bx = blockIdx.x * 32, by = blockIdx.y * 32;
    const int tx = threadIdx.x, ty = threadIdx.y;
    for (int r = ty; r < 32; r += 8) {
        int n = bx + tx;
        tile[r][tx] = (n < N) ? W[(size_t)(by + r) * N + n] : 0.0f;
    }
    __syncthreads();
    for (int r = ty; r < 32; r += 8) {
        int n = bx + r, k = by + tx;
        if (n < N) {
            float x = tile[tx][r] * SSCALE;
            __half h = __float2half_rn(x);
            WtH[(size_t)n * Kd + k] = h;
            WtL[(size_t)n * Kd + k] = __float2half_rn((x - __half2float(h)) * LOSCALE);
        }
    }
}

// ---------------- fp32 SGEMM (f32x2) — encoder; bit-identical to round 2 ----------------
// MODE 0: bias  MODE 1: bias+silu. SPLITOUT: also emit fp16 split of output.
template <int MODE, bool SPLITOUT>
__global__ void __launch_bounds__(256)
sgemm_k(const float* __restrict__ Ag, const float* __restrict__ Bg,
        const float* __restrict__ bias, float* __restrict__ Cg,
        int M, int N, int Kd, __half* __restrict__ hiP, __half* __restrict__ loP) {
    __shared__ float As[BKd][BM];
    __shared__ float Bs[BKd][BN];
    const int tid = threadIdx.x;
    const int rbase = blockIdx.y * BM, cbase = blockIdx.x * BN;
    const int rowA = tid >> 1, colA4 = (tid & 1) * 4;
    const int rowB = tid >> 5, colB4 = (tid & 31) * 4;
    const int tr = (tid >> 4) * TM, tc = (tid & 15) * TN;

    u64 acc[TM][TN / 2];
#pragma unroll
    for (int i = 0; i < TM; i++)
#pragma unroll
        for (int j = 0; j < TN / 2; j++) acc[i][j] = 0ull;

    const int nt = Kd / BKd;
    float4 pa = *reinterpret_cast<const float4*>(&Ag[(size_t)(rbase + rowA) * Kd + colA4]);
    float4 pb = make_float4(0.f, 0.f, 0.f, 0.f);
    if (cbase + colB4 < N)
        pb = *reinterpret_cast<const float4*>(&Bg[(size_t)rowB * N + cbase + colB4]);

    for (int t = 0; t < nt; t++) {
        __syncthreads();
        As[colA4 + 0][rowA] = pa.x; As[colA4 + 1][rowA] = pa.y;
        As[colA4 + 2][rowA] = pa.z; As[colA4 + 3][rowA] = pa.w;
        *reinterpret_cast<float4*>(&Bs[rowB][colB4]) = pb;
        __syncthreads();
        if (t + 1 < nt) {
            pa = *reinterpret_cast<const float4*>(&Ag[(size_t)(rbase + rowA) * Kd + (t + 1) * BKd + colA4]);
            if (cbase + colB4 < N)
                pb = *reinterpret_cast<const float4*>(&Bg[(size_t)((t + 1) * BKd + rowB) * N + cbase + colB4]);
        }
#pragma unroll
        for (int k = 0; k < BKd; k++) {
            float4 a0 = *reinterpret_cast<const float4*>(&As[k][tr]);
            float4 a1 = *reinterpret_cast<const float4*>(&As[k][tr + 4]);
            const u64* bp = reinterpret_cast<const u64*>(&Bs[k][tc]);
            u64 b0 = bp[0], b1 = bp[1], b2 = bp[2], b3 = bp[3];
            float am[TM] = {a0.x, a0.y, a0.z, a0.w, a1.x, a1.y, a1.z, a1.w};
#pragma unroll
            for (int i = 0; i < TM; i++) {
                u64 ap = pack2(am[i], am[i]);
                fma2(acc[i][0], ap, b0); fma2(acc[i][1], ap, b1);
                fma2(acc[i][2], ap, b2); fma2(acc[i][3], ap, b3);
            }
        }
    }

#pragma unroll
    for (int i = 0; i < TM; i++) {
        const int row = rbase + tr + i;
#pragma unroll
        for (int j = 0; j < TN / 2; j++) {
            const int c0 = cbase + tc + 2 * j;
            if (c0 < N) {
                float lo, hi; unpack2(acc[i][j], lo, hi);
                float v0 = lo + bias[c0], v1 = hi + bias[c0 + 1];
                if (MODE == 1) { v0 = silu_f(v0); v1 = silu_f(v1); }
                Cg[(size_t)row * N + c0]     = v0;
                Cg[(size_t)row * N + c0 + 1] = v1;
                if (SPLITOUT) {
                    float x0 = v0 * SSCALE, x1 = v1 * SSCALE;
                    __half h0 = __float2half_rn(x0), h1 = __float2half_rn(x1);
                    *reinterpret_cast<__half2*>(&hiP[(size_t)row * N + c0]) = __half2(h0, h1);
                    *reinterpret_cast<__half2*>(&loP[(size_t)row * N + c0]) =
                        __half2(__float2half_rn((x0 - __half2float(h0)) * LOSCALE),
                                __float2half_rn((x1 - __half2float(h1)) * LOSCALE));
                }
            }
        }
    }
}

// ---------------- split-fp16 HMMA GEMM — decoder ----------------
// MODE 1: silu, write SPLIT outputs only.  MODE 2: write fp32 out + recon loss.
template <int MODE>
__global__ void __launch_bounds__(256)
mma_gemm(const __half* __restrict__ Ah, const __half* __restrict__ Al,
         const __half* __restrict__ Bh, const __half* __restrict__ Bl,
         const float* __restrict__ bias, float* __restrict__ Cg,
         __half* __restrict__ hiP, __half* __restrict__ loP,
         int M, int N, int Kd, const float* __restrict__ ref) {
    constexpr int KP = 40;
    __shared__ __half As[128 * KP];
    __shared__ __half Bs[128 * KP];

    const int tid = threadIdx.x;
    const int lane = tid & 31, warp = tid >> 5;
    const int wm = warp >> 2, wn = warp & 3;
    const int gq = lane >> 2, tq = lane & 3;
    const int rbase = blockIdx.y * 128, cbase = blockIdx.x * 128;

    const int KC = Kd >> 5;
    const int NCH = 3 * KC;

    float acc[4][4][4];
#pragma unroll
    for (int a = 0; a < 4; a++)
#pragma unroll
        for (int b = 0; b < 4; b++)
#pragma unroll
            for (int c = 0; c < 4; c++) acc[a][b][c] = 0.0f;

    uint4 pa[2], pb[2];
    const uint4 z4 = make_uint4(0, 0, 0, 0);

    auto loadAB = [&](int c) {
        const int p = c / KC, kc = c % KC;
        const __half* Asrc = (p == 1) ? Al : Ah;
        const __half* Bsrc = (p == 0) ? Bl : Bh;
#pragma unroll
        for (int j = 0; j < 2; j++) {
            int i = tid + 256 * j;
            int row = i >> 2, seg = i & 3;
            pa[j] = *reinterpret_cast<const uint4*>(
                Asrc + (size_t)(rbase + row) * Kd + kc * 32 + seg * 8);
            int col = cbase + row;
            pb[j] = (col < N) ? *reinterpret_cast<const uint4*>(
                Bsrc + (size_t)col * Kd + kc * 32 + seg * 8) : z4;
        }
    };

    loadAB(0);
    for (int c = 0; c < NCH; c++) {
        __syncthreads();
#pragma unroll
        for (int j = 0; j < 2; j++) {
            int i = tid + 256 * j;
            int row = i >> 2, seg = i & 3;
            *reinterpret_cast<uint4*>(As + row * KP + seg * 8) = pa[j];
            *reinterpret_cast<uint4*>(Bs + row * KP + seg * 8) = pb[j];
        }
        __syncthreads();
        if (c + 1 < NCH) loadAB(c + 1);
        if (c == 2 * KC) {
#pragma unroll
            for (int a = 0; a < 4; a++)
#pragma unroll
                for (int b = 0; b < 4; b++)
#pragma unroll
                    for (int q = 0; q < 4; q++) acc[a][b][q] *= INV_LO;
        }
#pragma unroll
        for (int ks = 0; ks < 2; ks++) {
            uint32_t af[4][4];
#pragma unroll
            for (int mt = 0; mt < 4; mt++) {
                const __half* ap = As + (wm * 64 + mt * 16 + gq) * KP + ks * 16 + tq * 2;
                af[mt][0] = *reinterpret_cast<const uint32_t*>(ap);
                af[mt][1] = *reinterpret_cast<const uint32_t*>(ap + 8 * KP);
                af[mt][2] = *reinterpret_cast<const uint32_t*>(ap + 8);
                af[mt][3] = *reinterpret_cast<const uint32_t*>(ap + 8 * KP + 8);
            }
#pragma unroll
            for (int nt = 0; nt < 4; nt++) {
                const __half* bp = Bs + (wn * 32 + nt * 8 + gq) * KP + ks * 16 + tq * 2;
                uint32_t b0 = *reinterpret_cast<const uint32_t*>(bp);
                uint32_t b1 = *reinterpret_cast<const uint32_t*>(bp + 8);
#pragma unroll
                for (int mt = 0; mt < 4; mt++)
                    mma16816(acc[mt][nt], af[mt][0], af[mt][1], af[mt][2], af[mt][3], b0, b1);
            }
        }
    }

    float lsum = 0.0f;
#pragma unroll
    for (int mt = 0; mt < 4; mt++) {
#pragma unroll
        for (int nt = 0; nt < 4; nt++) {
            const int row0 = rbase + wm * 64 + mt * 16 + gq;
            const int col0 = cbase + wn * 32 + nt * 8 + tq * 2;
            if (col0 < N) {
                const float bz0 = bias[col0], bz1 = bias[col0 + 1];
#pragma unroll
                for (int h = 0; h < 2; h++) {
                    const int row = row0 + 8 * h;
                    float v0 = acc[mt][nt][2 * h + 0] * INV_FULL + bz0;
                    float v1 = acc[mt][nt][2 * h + 1] * INV_FULL + bz1;
                    if (MODE == 1) {
                        v0 = silu_f(v0); v1 = silu_f(v1);
                        float x0 = v0 * SSCALE, x1 = v1 * SSCALE;
                        __half h0 = __float2half_rn(x0), h1 = __float2half_rn(x1);
                        *reinterpret_cast<__half2*>(&hiP[(size_t)row * N + col0]) = __half2(h0, h1);
                        *reinterpret_cast<__half2*>(&loP[(size_t)row * N + col0]) =
                            __half2(__float2half_rn((x0 - __half2float(h0)) * LOSCALE),
                                    __float2half_rn((x1 - __half2float(h1)) * LOSCALE));
                    } else {
                        Cg[(size_t)row * N + col0]     = v0;
                        Cg[(size_t)row * N + col0 + 1] = v1;
                        float d0 = v0 - ref[(size_t)row * N + col0];
                        float d1 = v1 - ref[(size_t)row * N + col0 + 1];
                        lsum = fmaf(d0, d0, fmaf(d1, d1, lsum));
                    }
                }
            }
        }
    }
    if (MODE == 2) {
        __shared__ float red[256];
        red[tid] = lsum; __syncthreads();
        for (int s = 128; s > 0; s >>= 1) { if (tid < s) red[tid] += red[tid + s]; __syncthreads(); }
        if (tid == 0) atomicAdd(&g_recon_sum, red[0]);
    }
}

// ---------------- HMMA argmin ----------------
static constexpr int KPA = 136;
static constexpr int KPB = 40;
static constexpr int ARG_SMEM =
    (2 * 128 * KPA + 128 * KPB) * 2 + (cK + 128 * 4 * 3) * 4;  // 102400

__global__ void __launch_bounds__(256)
argmin_mma() {
    extern __shared__ __align__(16) char dsm[];
    __half* a_h = reinterpret_cast<__half*>(dsm);
    __half* a_l = a_h + 128 * KPA;
    __half* bs  = a_l + 128 * KPA;
    float*  cn_s = reinterpret_cast<float*>(bs + 128 * KPB);
    float*  RV = cn_s + cK;
    float*  RS = RV + 512;
    int*    RI = reinterpret_cast<int*>(RS + 512);

    const int tid = threadIdx.x;
    const int lane = tid & 31, warp = tid >> 5;
    const int wm = warp >> 2, wn = warp & 3;
    const int gq = lane >> 2, tq = lane & 3;
    const int rbase = blockIdx.x * 128;

#pragma unroll
    for (int j = 0; j < 8; j++) {
        int i = tid + 256 * j;
        int row = i >> 4, seg = i & 15;
        *reinterpret_cast<uint4*>(a_h + row * KPA + seg * 8) =
            *reinterpret_cast<const uint4*>(g_latH + (size_t)(rbase + row) * cD + seg * 8);
        *reinterpret_cast<uint4*>(a_l + row * KPA + seg * 8) =
            *reinterpret_cast<const uint4*>(g_latL + (size_t)(rbase + row) * cD + seg * 8);
    }
    for (int i = tid; i < cK / 4; i += 256) {
        float4 v = reinterpret_cast<const float4*>(g_cn)[i];
        v.x *= 65536.0f; v.y *= 65536.0f; v.z *= 65536.0f; v.w *= 65536.0f;
        reinterpret_cast<float4*>(cn_s)[i] = v;
    }

    float rnr[4][2];
#pragma unroll
    for (int mt = 0; mt < 4; mt++)
#pragma unroll
        for (int h = 0; h < 2; h++)
            rnr[mt][h] = g_rn[rbase + wm * 64 + mt * 16 + gq + 8 * h] * 65536.0f;

    float bv[4][2], sv[4][2];
    int   bi[4][2];
#pragma unroll
    for (int mt = 0; mt < 4; mt++)
#pragma unroll
        for (int h = 0; h < 2; h++) { bv[mt][h] = INFINITY; sv[mt][h] = INFINITY; bi[mt][h] = 0; }

    float acc[4][4][4];
#pragma unroll
    for (int a = 0; a < 4; a++)
#pragma unroll
        for (int b = 0; b < 4; b++)
#pragma unroll
            for (int q = 0; q < 4; q++) acc[a][b][q] = 0.0f;

    uint4 pb[2];
    auto loadB = [&](int c) {
        const int ct = c / 12, sub = c % 12;
        const int p = sub >> 2, kc = sub & 3;
        const __half* src = (p == 0) ? g_cbL : g_cbH;
#pragma unroll
        for (int j = 0; j < 2; j++) {
            int i = tid + 256 * j;
            int row = i >> 2, seg = i & 3;
            pb[j] = *reinterpret_cast<const uint4*>(
                src + (size_t)(ct * 128 + row) * cD + kc * 32 + seg * 8);
        }
    };

    loadB(0);
    for (int c = 0; c < 32 * 12; c++) {
        const int sub = c % 12;
        __syncthreads();
#pragma unroll
        for (int j = 0; j < 2; j++) {
            int i = tid + 256 * j;
            int row = i >> 2, seg = i & 3;
            *reinterpret_cast<uint4*>(bs + row * KPB + seg * 8) = pb[j];
        }
        __syncthreads();
        if (c + 1 < 32 * 12) loadB(c + 1);
        if (sub == 8) {
#pragma unroll
            for (int a = 0; a < 4; a++)
#pragma unroll
                for (int b = 0; b < 4; b++)
#pragma unroll
                    for (int q = 0; q < 4; q++) acc[a][b][q] *= INV_LO;
        }
        const int p = sub >> 2, kc = sub & 3;
        const __half* Abase = (p == 1) ? a_l : a_h;
#pragma unroll
        for (int ks = 0; ks < 2; ks++) {
            const int k0 = kc * 32 + ks * 16;
            uint32_t af[4][4];
#pragma unroll
            for (int mt = 0; mt < 4; mt++) {
                const __half* ap = Abase + (wm * 64 + mt * 16 + gq) * KPA + k0 + tq * 2;
                af[mt][0] = *reinterpret_cast<const uint32_t*>(ap);
                af[mt][1] = *reinterpret_cast<const uint32_t*>(ap + 8 * KPA);
                af[mt][2] = *reinterpret_cast<const uint32_t*>(ap + 8);
                af[mt][3] = *reinterpret_cast<const uint32_t*>(ap + 8 * KPA + 8);
            }
#pragma unroll
            for (int nt = 0; nt < 4; nt++) {
                const __half* bp = bs + (wn * 32 + nt * 8 + gq) * KPB + ks * 16 + tq * 2;
                uint32_t b0 = *reinterpret_cast<const uint32_t*>(bp);
                uint32_t b1 = *reinterpret_cast<const uint32_t*>(bp + 8);
#pragma unroll
                for (int mt = 0; mt < 4; mt++)
                    mma16816(acc[mt][nt], af[mt][0], af[mt][1], af[mt][2], af[mt][3], b0, b1);
            }
        }
        if (sub == 11) {
            const int ct = c / 12;
#pragma unroll
            for (int mt = 0; mt < 4; mt++) {
#pragma unroll
                for (int nt = 0; nt < 4; nt++) {
                    const int col0 = ct * 128 + wn * 32 + nt * 8 + tq * 2;
#pragma unroll
                    for (int h = 0; h < 2; h++) {
#pragma unroll
                        for (int cc = 0; cc < 2; cc++) {
                            const int kg = col0 + cc;
                            float s1 = __fadd_rn(rnr[mt][h], cn_s[kg]);
                            float d  = __fadd_rn(s1, -2.0f * acc[mt][nt][2 * h + cc]);
                            if (d < bv[mt][h] || (d == bv[mt][h] && kg < bi[mt][h])) {
                                sv[mt][h] = bv[mt][h]; bv[mt][h] = d; bi[mt][h] = kg;
                            } else if (d < sv[mt][h]) {
                                sv[mt][h] = d;
                            }
                        }
                    }
                    acc[mt][nt][0] = 0.0f; acc[mt][nt][1] = 0.0f;
                    acc[mt][nt][2] = 0.0f; acc[mt][nt][3] = 0.0f;
                }
            }
        }
    }

#pragma unroll
    for (int mt = 0; mt < 4; mt++) {
#pragma unroll
        for (int h = 0; h < 2; h++) {
            float b = bv[mt][h], s = sv[mt][h];
            int   i = bi[mt][h];
#pragma unroll
            for (int m = 1; m <= 2; m <<= 1) {
                float b2 = __shfl_xor_sync(0xffffffffu, b, m);
                float s2 = __shfl_xor_sync(0xffffffffu, s, m);
                int   i2 = __shfl_xor_sync(0xffffffffu, i, m);
                if (b2 < b || (b2 == b && i2 < i)) { s = fminf(b, s2); b = b2; i = i2; }
                else s = fminf(s, b2);
            }
            if (tq == 0) {
                const int rl = wm * 64 + mt * 16 + gq + 8 * h;
                RV[rl * 4 + wn] = b; RS[rl * 4 + wn] = s; RI[rl * 4 + wn] = i;
            }
        }
    }
    __syncthreads();
    if (tid < 128) {
        float b = RV[tid * 4], s = RS[tid * 4];
        int   i = RI[tid * 4];
#pragma unroll
        for (int w = 1; w < 4; w++) {
            float b2 = RV[tid * 4 + w], s2 = RS[tid * 4 + w];
            int   i2 = RI[tid * 4 + w];
            if (b2 < b || (b2 == b && i2 < i)) { s = fminf(b, s2); b = b2; i = i2; }
            else s = fminf(s, b2);
        }
        g_idx[rbase + tid] = i;
        if (s - b < EPS_SCALED) {
            int p = atomicAdd(&g_flagcnt, 1);
            g_flagrows[p] = rbase + tid;
        }
    }
}

// exact fp32 recheck (same k-order + epilogue rounding as the fp32 argmin of rounds 1-2)
__global__ void __launch_bounds__(256)
recheck_k(const float* __restrict__ cb) {
    __shared__ float lrow[cD];
    __shared__ float rv[256];
    __shared__ int   ri[256];
    const int tid = threadIdx.x;
    const int nf = g_flagcnt;
    for (int f = blockIdx.x; f < nf; f += gridDim.x) {
        const int row = g_flagrows[f];
        if (tid < 32)
            reinterpret_cast<float4*>(lrow)[tid] =
                reinterpret_cast<const float4*>(&g_lat[(size_t)row * cD])[tid];
        __syncthreads();
        const float rn = g_rn[row];
        float bvv = INFINITY; int bii = 0;
        for (int k = tid; k < cK; k += 256) {
            const float4* cp = reinterpret_cast<const float4*>(&cb[(size_t)k * cD]);
            float dot = 0.0f;
#pragma unroll
            for (int d4 = 0; d4 < 32; d4++) {
                float4 cv = cp[d4];
                dot = fmaf(lrow[d4 * 4 + 0], cv.x, dot);
                dot = fmaf(lrow[d4 * 4 + 1], cv.y, dot);
                dot = fmaf(lrow[d4 * 4 + 2], cv.z, dot);
                dot = fmaf(lrow[d4 * 4 + 3], cv.w, dot);
            }
            float s1 = __fadd_rn(rn, g_cn[k]);
            float dd = __fadd_rn(s1, -2.0f * dot);
            if (dd < bvv || (dd == bvv && k < bii)) { bvv = dd; bii = k; }
        }
        rv[tid] = bvv; ri[tid] = bii;
        __syncthreads();
        for (int s = 128; s > 0; s >>= 1) {
            if (tid < s) {
                float v = rv[tid + s]; int ix = ri[tid + s];
                if (v < rv[tid] || (v == rv[tid] && ix < ri[tid])) { rv[tid] = v; ri[tid] = ix; }
            }
            __syncthreads();
        }
        if (tid == 0) g_idx[row] = ri[0];
        __syncthreads();
    }
}

__global__ void gather_vq(const float* __restrict__ cb, float* __restrict__ outIdxF) {
    int warp = (blockIdx.x * blockDim.x + threadIdx.x) >> 5;
    int lane = threadIdx.x & 31;
    if (warp >= cROWS) return;
    int id = g_idx[warp];
    float4 c = reinterpret_cast<const float4*>(cb)[(size_t)id * 32 + lane];
    float4 l = reinterpret_cast<const float4*>(g_lat)[(size_t)warp * 32 + lane];
    if (lane < 16) {
        reinterpret_cast<uint4*>(g_qH + (size_t)warp * cD)[lane] =
            reinterpret_cast<const uint4*>(g_cbH + (size_t)id * cD)[lane];
    } else {
        reinterpret_cast<uint4*>(g_qL + (size_t)warp * cD)[lane - 16] =
            reinterpret_cast<const uint4*>(g_cbL + (size_t)id * cD)[lane - 16];
    }
    float dx = c.x - l.x, dy = c.y - l.y, dz = c.z - l.z, dw = c.w - l.w;
    float s = dx * dx + dy * dy + dz * dz + dw * dw;
#pragma unroll
    for (int off = 16; off > 0; off >>= 1) s += __shfl_down_sync(0xffffffffu, s, off);
    if (lane == 0) {
        atomicAdd(&g_vq_sum, s);
        if (outIdxF) outIdxF[warp] = (float)id;
    }
}

__global__ void finalize_k(float* __restrict__ out, int out_size) {
    if (out_size >= FULL_OUT) {
        float m = g_vq_sum / (float)(cB * cN * cD);
        float vq = 1.25f * m;
        float rl = g_recon_sum / (float)RECON_ELEMS;
        out[SCALAR_OFF + 0] = vq;
        out[SCALAR_OFF + 1] = rl;
        out[SCALAR_OFF + 2] = rl + vq;
    }
}

// ---------------- launch ----------------
extern "C" void kernel_launch(void* const* d_in, const int* in_sizes, int n_in,
                              void* d_out, int out_size) {
    const float* actions = (const float*)d_in[0];
    const float* e_w1 = (const float*)d_in[1];
    const float* e_b1 = (const float*)d_in[2];
    const float* e_w2 = (const float*)d_in[3];
    const float* e_b2 = (const float*)d_in[4];
    const float* e_w3 = (const float*)d_in[5];
    const float* e_b3 = (const float*)d_in[6];
    const float* cb   = (const float*)d_in[7];
    const float* d_w1 = (const float*)d_in[8];
    const float* d_b1 = (const float*)d_in[9];
    const float* d_w2 = (const float*)d_in[10];
    const float* d_b2 = (const float*)d_in[11];
    const float* d_w3 = (const float*)d_in[12];
    const float* d_b3 = (const float*)d_in[13];
    float* out = (float*)d_out;

    float *p_h1, *p_h2, *p_lat;
    cudaGetSymbolAddress((void**)&p_h1,  g_h1);
    cudaGetSymbolAddress((void**)&p_h2,  g_h2);
    cudaGetSymbolAddress((void**)&p_lat, g_lat);
    __half *latH, *latL, *qH, *qL, *g1H, *g1L, *g2H, *g2L, *cbH, *cbL;
    __half *v1H, *v1L, *v2H, *v2L, *v3H, *v3L;
    cudaGetSymbolAddress((void**)&latH, g_latH); cudaGetSymbolAddress((void**)&latL, g_latL);
    cudaGetSymbolAddress((void**)&qH, g_qH);     cudaGetSymbolAddress((void**)&qL, g_qL);
    cudaGetSymbolAddress((void**)&g1H, g_g1H);   cudaGetSymbolAddress((void**)&g1L, g_g1L);
    cudaGetSymbolAddress((void**)&g2H, g_g2H);   cudaGetSymbolAddress((void**)&g2L, g_g2L);
    cudaGetSymbolAddress((void**)&cbH, g_cbH);   cudaGetSymbolAddress((void**)&cbL, g_cbL);
    cudaGetSymbolAddress((void**)&v1H, g_v1H);   cudaGetSymbolAddress((void**)&v1L, g_v1L);
    cudaGetSymbolAddress((void**)&v2H, g_v2H);   cudaGetSymbolAddress((void**)&v2L, g_v2L);
    cudaGetSymbolAddress((void**)&v3H, g_v3H);   cudaGetSymbolAddress((void**)&v3L, g_v3L);

    static bool attr_done = false;
    if (!attr_done) {
        cudaFuncSetAttribute(argmin_mma, cudaFuncAttributeMaxDynamicSharedMemorySize, ARG_SMEM);
        attr_done = true;
    }

    const bool has_idx = out_size >= (IDX_OFF + cROWS);

    init_accum<<<1, 1>>>();
    cn_kernel<<<cK / 8, 256>>>(cb);
    split_act<<<(cK * cD / 4 + 255) / 256, 256>>>(cb, cbH, cbL, cK * cD / 4);
    dim3 wt(32, 8);
    wsplit<<<dim3(cHID / 32, cLAT / 32), wt>>>(d_w1, v1H, v1L, cLAT, cHID);
    wsplit<<<dim3(cHID / 32, cHID / 32), wt>>>(d_w2, v2H, v2L, cHID, cHID);
    wsplit<<<dim3(cFLAT / 32 + 1, cHID / 32), wt>>>(d_w3, v3H, v3L, cHID, cFLAT);

    // encoder — fp32, bit-identical to round 2
    sgemm_k<1, false><<<dim3(cHID / BN, cB / BM), 256>>>(actions, e_w1, e_b1, p_h1, cB, cHID, cFLAT, nullptr, nullptr);
    sgemm_k<1, false><<<dim3(cHID / BN, cB / BM), 256>>>(p_h1, e_w2, e_b2, p_h2, cB, cHID, cHID, nullptr, nullptr);
    sgemm_k<0, true><<<dim3(cLAT / BN, cB / BM), 256>>>(p_h2, e_w3, e_b3, p_lat, cB, cLAT, cHID, latH, latL);

    // quantization — HMMA + exact recheck
    rn_kernel<<<cROWS / 8, 256>>>();
    argmin_mma<<<cROWS / 128, 256, ARG_SMEM>>>();
    recheck_k<<<256, 256>>>(cb);
    gather_vq<<<cROWS / 8, 256>>>(cb, has_idx ? (out + IDX_OFF) : nullptr);

    // decoder — split-fp16 HMMA
    mma_gemm<1><<<dim3(cHID / 128, cB / 128), 256>>>(qH, qL, v1H, v1L, d_b1, nullptr, g1H, g1L, cB, cHID, cLAT, nullptr);
    mma_gemm<1><<<dim3(cHID / 128, cB / 128), 256>>>(g1H, g1L, v2H, v2L, d_b2, nullptr, g2H, g2L, cB, cHID, cHID, nullptr);
    mma_gemm<2><<<dim3(1, cB / 128), 256>>>(g2H, g2L, v3H, v3L, d_b3, out, nullptr, nullptr, cB, cFLAT, cHID, actions);

    finalize_k<<<1, 1>>>(out, out_size);
}